// round 1
// baseline (speedup 1.0000x reference)
#include <cuda_runtime.h>
#include <cstdint>

#define dE 8
#define dH 1024
#define dI 4096
#define dN 2048
#define dK 2
#define dNK 4096

#define BM 128
#define BN 64
#define BK 16
#define PA 4
#define PB 4
#define NTHREADS 256

// ---- scratch (device globals; no runtime allocation) ----
__device__ int   g_pairs[dNK];                 // pair ids grouped by expert
__device__ int   g_off[dE + 1];                // expert offsets
__device__ float g_h[(size_t)dNK * dI];        // SwiGLU hidden, indexed by slot   (64 MB)
__device__ float g_y[(size_t)dNK * dH];        // per-pair weighted output, by pair (16 MB)

__device__ __forceinline__ uint32_t smem_u32(const void* p) {
    return (uint32_t)__cvta_generic_to_shared(p);
}
__device__ __forceinline__ void cpa16(uint32_t dst, const void* src, bool pred) {
    int sz = pred ? 16 : 0;
    asm volatile("cp.async.cg.shared.global [%0], [%1], 16, %2;\n"
                 :: "r"(dst), "l"(src), "r"(sz));
}
__device__ __forceinline__ void cpa_commit() { asm volatile("cp.async.commit_group;\n"); }
__device__ __forceinline__ void cpa_wait1()  { asm volatile("cp.async.wait_group 1;\n"); }

__device__ __forceinline__ uint32_t f2tf32(float f) {
    uint32_t u;
    asm("cvt.rna.tf32.f32 %0, %1;" : "=r"(u) : "f"(f));
    return u;
}
__device__ __forceinline__ void mma_tf32(float* d, const uint32_t* a, const uint32_t* b) {
    asm volatile("mma.sync.aligned.m16n8k8.row.col.f32.tf32.tf32.f32 "
                 "{%0,%1,%2,%3}, {%4,%5,%6,%7}, {%8,%9}, {%0,%1,%2,%3};\n"
                 : "+f"(d[0]), "+f"(d[1]), "+f"(d[2]), "+f"(d[3])
                 : "r"(a[0]), "r"(a[1]), "r"(a[2]), "r"(a[3]),
                   "r"(b[0]), "r"(b[1]));
}

// ---- routing: histogram + scan + scatter, single CTA ----
__global__ void route_kernel(const int* __restrict__ idx) {
    __shared__ int s_cnt[dE], s_base[dE];
    int t = threadIdx.x;
    if (t < dE) s_cnt[t] = 0;
    __syncthreads();
    for (int p = t; p < dNK; p += blockDim.x) atomicAdd(&s_cnt[idx[p]], 1);
    __syncthreads();
    if (t == 0) {
        int acc = 0;
        for (int e = 0; e < dE; ++e) { g_off[e] = acc; s_base[e] = acc; acc += s_cnt[e]; }
        g_off[dE] = acc;
    }
    __syncthreads();
    if (t < dE) s_cnt[t] = 0;   // reuse as cursors
    __syncthreads();
    for (int p = t; p < dNK; p += blockDim.x) {
        int e = idx[p];
        int slot = s_base[e] + atomicAdd(&s_cnt[e], 1);
        g_pairs[slot] = p;
    }
}

// ---- GEMM1: h[slot, :] = silu(x_row @ w1[e]) * (x_row @ w3[e]) ----
__global__ __launch_bounds__(NTHREADS, 2)
void gemm1_kernel(const float* __restrict__ x,
                  const float* __restrict__ w1,
                  const float* __restrict__ w3) {
    const int e    = blockIdx.z;
    const int mEnd = g_off[e + 1];
    const int m0   = g_off[e] + blockIdx.y * BM;
    if (m0 >= mEnd) return;
    const int i0 = blockIdx.x * BN;

    __shared__ __align__(16) float sA [2][BM][BK + PA];
    __shared__ __align__(16) float sB1[2][BK][BN + PB];
    __shared__ __align__(16) float sB3[2][BK][BN + PB];
    __shared__ int s_tok[BM];

    const int t = threadIdx.x;
    if (t < BM) {
        int slot = m0 + t;
        s_tok[t] = (slot < mEnd) ? (g_pairs[slot] / dK) : -1;
    }
    __syncthreads();

    const float* w1e = w1 + (size_t)e * dH * dI + i0;
    const float* w3e = w3 + (size_t)e * dH * dI + i0;

    auto load_stage = [&](int s, int kt) {
        const int k0 = kt * BK;
        #pragma unroll
        for (int it = 0; it < 2; ++it) {
            int id = t + it * NTHREADS;
            int row = id >> 2, ch = id & 3;
            int tok = s_tok[row];
            const float* src = x + (size_t)(tok < 0 ? 0 : tok) * dH + k0 + ch * 4;
            cpa16(smem_u32(&sA[s][row][ch * 4]), src, tok >= 0);
        }
        {
            int row = t >> 4, ch = t & 15;
            cpa16(smem_u32(&sB1[s][row][ch * 4]), w1e + (size_t)(k0 + row) * dI + ch * 4, true);
            cpa16(smem_u32(&sB3[s][row][ch * 4]), w3e + (size_t)(k0 + row) * dI + ch * 4, true);
        }
    };

    const int w = t >> 5, l = t & 31;
    const int wm = w & 3, wn = w >> 2;
    const int lr = l >> 2, lc = l & 3;

    float accG[2][4][4] = {};
    float accU[2][4][4] = {};

    const int KT = dH / BK;
    load_stage(0, 0);
    cpa_commit();

    for (int kt = 0; kt < KT; ++kt) {
        if (kt + 1 < KT) load_stage((kt + 1) & 1, kt + 1);
        cpa_commit();
        cpa_wait1();
        __syncthreads();
        const int s = kt & 1;
        #pragma unroll
        for (int ks = 0; ks < BK / 8; ++ks) {
            uint32_t af[2][4];
            #pragma unroll
            for (int mi = 0; mi < 2; ++mi) {
                int r = wm * 32 + mi * 16 + lr;
                int c = ks * 8 + lc;
                af[mi][0] = f2tf32(sA[s][r][c]);
                af[mi][1] = f2tf32(sA[s][r + 8][c]);
                af[mi][2] = f2tf32(sA[s][r][c + 4]);
                af[mi][3] = f2tf32(sA[s][r + 8][c + 4]);
            }
            #pragma unroll
            for (int ni = 0; ni < 4; ++ni) {
                int col = wn * 32 + ni * 8 + lr;
                int kk  = ks * 8 + lc;
                uint32_t b1f[2], b3f[2];
                b1f[0] = f2tf32(sB1[s][kk][col]);
                b1f[1] = f2tf32(sB1[s][kk + 4][col]);
                b3f[0] = f2tf32(sB3[s][kk][col]);
                b3f[1] = f2tf32(sB3[s][kk + 4][col]);
                #pragma unroll
                for (int mi = 0; mi < 2; ++mi) {
                    mma_tf32(accG[mi][ni], af[mi], b1f);
                    mma_tf32(accU[mi][ni], af[mi], b3f);
                }
            }
        }
        __syncthreads();
    }

    #pragma unroll
    for (int mi = 0; mi < 2; ++mi) {
        int r0 = m0 + wm * 32 + mi * 16 + lr;
        int r1 = r0 + 8;
        #pragma unroll
        for (int ni = 0; ni < 4; ++ni) {
            int c = i0 + wn * 32 + ni * 8 + lc * 2;
            if (r0 < mEnd) {
                float g0 = accG[mi][ni][0], g1 = accG[mi][ni][1];
                float u0 = accU[mi][ni][0], u1 = accU[mi][ni][1];
                float2 h;
                h.x = g0 / (1.0f + __expf(-g0)) * u0;
                h.y = g1 / (1.0f + __expf(-g1)) * u1;
                *(float2*)&g_h[(size_t)r0 * dI + c] = h;
            }
            if (r1 < mEnd) {
                float g2 = accG[mi][ni][2], g3 = accG[mi][ni][3];
                float u2 = accU[mi][ni][2], u3 = accU[mi][ni][3];
                float2 h;
                h.x = g2 / (1.0f + __expf(-g2)) * u2;
                h.y = g3 / (1.0f + __expf(-g3)) * u3;
                *(float2*)&g_h[(size_t)r1 * dI + c] = h;
            }
        }
    }
}

// ---- GEMM2: y[pair, :] = ew[pair] * (h[slot, :] @ w2[e]) ----
__global__ __launch_bounds__(NTHREADS, 2)
void gemm2_kernel(const float* __restrict__ ew,
                  const float* __restrict__ w2) {
    const int e    = blockIdx.z;
    const int mEnd = g_off[e + 1];
    const int m0   = g_off[e] + blockIdx.y * BM;
    if (m0 >= mEnd) return;
    const int h0 = blockIdx.x * BN;

    __shared__ __align__(16) float sA[2][BM][BK + PA];
    __shared__ __align__(16) float sB[2][BK][BN + PB];

    const int t = threadIdx.x;
    const float* w2e = w2 + (size_t)e * dI * dH + h0;

    auto load_stage = [&](int s, int kt) {
        const int k0 = kt * BK;
        #pragma unroll
        for (int it = 0; it < 2; ++it) {
            int id = t + it * NTHREADS;
            int row = id >> 2, ch = id & 3;
            bool v = (m0 + row) < mEnd;
            const float* src = g_h + (size_t)(v ? (m0 + row) : 0) * dI + k0 + ch * 4;
            cpa16(smem_u32(&sA[s][row][ch * 4]), src, v);
        }
        {
            int row = t >> 4, ch = t & 15;
            cpa16(smem_u32(&sB[s][row][ch * 4]), w2e + (size_t)(k0 + row) * dH + ch * 4, true);
        }
    };

    const int w = t >> 5, l = t & 31;
    const int wm = w & 3, wn = w >> 2;
    const int lr = l >> 2, lc = l & 3;

    float acc[2][4][4] = {};

    const int KT = dI / BK;
    load_stage(0, 0);
    cpa_commit();

    for (int kt = 0; kt < KT; ++kt) {
        if (kt + 1 < KT) load_stage((kt + 1) & 1, kt + 1);
        cpa_commit();
        cpa_wait1();
        __syncthreads();
        const int s = kt & 1;
        #pragma unroll
        for (int ks = 0; ks < BK / 8; ++ks) {
            uint32_t af[2][4];
            #pragma unroll
            for (int mi = 0; mi < 2; ++mi) {
                int r = wm * 32 + mi * 16 + lr;
                int c = ks * 8 + lc;
                af[mi][0] = f2tf32(sA[s][r][c]);
                af[mi][1] = f2tf32(sA[s][r + 8][c]);
                af[mi][2] = f2tf32(sA[s][r][c + 4]);
                af[mi][3] = f2tf32(sA[s][r + 8][c + 4]);
            }
            #pragma unroll
            for (int ni = 0; ni < 4; ++ni) {
                int col = wn * 32 + ni * 8 + lr;
                int kk  = ks * 8 + lc;
                uint32_t bf[2];
                bf[0] = f2tf32(sB[s][kk][col]);
                bf[1] = f2tf32(sB[s][kk + 4][col]);
                #pragma unroll
                for (int mi = 0; mi < 2; ++mi) {
                    mma_tf32(acc[mi][ni], af[mi], bf);
                }
            }
        }
        __syncthreads();
    }

    #pragma unroll
    for (int mi = 0; mi < 2; ++mi) {
        int r0 = m0 + wm * 32 + mi * 16 + lr;
        int r1 = r0 + 8;
        int p0 = -1, p1 = -1;
        float wg0 = 0.0f, wg1 = 0.0f;
        if (r0 < mEnd) { p0 = g_pairs[r0]; wg0 = ew[p0]; }
        if (r1 < mEnd) { p1 = g_pairs[r1]; wg1 = ew[p1]; }
        #pragma unroll
        for (int ni = 0; ni < 4; ++ni) {
            int c = h0 + wn * 32 + ni * 8 + lc * 2;
            if (p0 >= 0) {
                float2 v = { wg0 * acc[mi][ni][0], wg0 * acc[mi][ni][1] };
                *(float2*)&g_y[(size_t)p0 * dH + c] = v;
            }
            if (p1 >= 0) {
                float2 v = { wg1 * acc[mi][ni][2], wg1 * acc[mi][ni][3] };
                *(float2*)&g_y[(size_t)p1 * dH + c] = v;
            }
        }
    }
}

// ---- final reduce over top-k: out[n] = y[2n] + y[2n+1] ----
__global__ void reduce_kernel(float* __restrict__ out) {
    int i = blockIdx.x * blockDim.x + threadIdx.x;  // over N*H/4
    if (i >= dN * dH / 4) return;
    int n  = i / (dH / 4);
    int hg = i % (dH / 4);
    const float4* y0 = (const float4*)&g_y[(size_t)(2 * n) * dH];
    const float4* y1 = (const float4*)&g_y[(size_t)(2 * n + 1) * dH];
    float4 a = y0[hg], b = y1[hg];
    float4 r = { a.x + b.x, a.y + b.y, a.z + b.z, a.w + b.w };
    ((float4*)out)[i] = r;
}

extern "C" void kernel_launch(void* const* d_in, const int* in_sizes, int n_in,
                              void* d_out, int out_size) {
    const float* x   = (const float*)d_in[0];
    const int*   idx = (const int*)  d_in[1];
    const float* ew  = (const float*)d_in[2];
    const float* w1  = (const float*)d_in[3];
    const float* w2  = (const float*)d_in[4];
    const float* w3  = (const float*)d_in[5];
    float* out = (float*)d_out;

    route_kernel<<<1, 256>>>(idx);
    dim3 g1(dI / BN, dNK / BM, dE);   // 64 x 32 x 8, empty tiles early-exit
    gemm1_kernel<<<g1, NTHREADS>>>(x, w1, w3);
    dim3 g2(dH / BN, dNK / BM, dE);   // 16 x 32 x 8
    gemm2_kernel<<<g2, NTHREADS>>>(ew, w2);
    reduce_kernel<<<(dN * dH / 4 + 255) / 256, 256>>>(out);
}